// round 3
// baseline (speedup 1.0000x reference)
#include <cuda_runtime.h>
#include <cuda_bf16.h>

// MyConv2D: NCHW direct conv, VALID, stride 1.
// x: [64, 64, 64, 64] f32, weight: [128, 64, 3, 3] f32, bias: [128,1,1] f32
// out: [64, 128, 62, 62] f32
//
// Strategy: register-blocked fp32 direct conv.
//   CTA: 256 threads, computes 64 out-channels x (8 rows x 32 cols) of one batch.
//   Thread: 8 co x (2 rows x 4 cols) = 64 accumulators.
//   Loop over input channels in chunks of 8; input tile + transposed weight
//   chunk staged in shared memory. Per (ci,ky): load a 2x6 input register
//   window (vector LDS) reused across the 3 kx taps; weights broadcast via
//   LDS.128 (warp-uniform address). 192 FFMA per ~20 aux instructions.

namespace {

constexpr int BATCH  = 64;
constexpr int CI     = 64;
constexpr int CO     = 128;
constexpr int H      = 64;
constexpr int W      = 64;
constexpr int OH     = 62;
constexpr int OW     = 62;

constexpr int TH     = 8;    // output rows per CTA tile
constexpr int TW     = 32;   // output cols per CTA tile
constexpr int CO_T   = 64;   // out-channels per CTA tile
constexpr int CI_C   = 8;    // input-channel chunk per smem stage

constexpr int IN_ROWS   = TH + 2;  // 10
constexpr int IN_COLS   = TW + 2;  // 34
constexpr int IN_STRIDE = 36;      // pad: keeps rows 16B-aligned (36*4=144B)

constexpr int THREADS = 256;

__global__ __launch_bounds__(THREADS, 2)
void conv2d_k3_kernel(const float* __restrict__ x,
                      const float* __restrict__ wgt,
                      const float* __restrict__ bias,
                      float* __restrict__ out) {
    __shared__ __align__(16) float s_in[CI_C * IN_ROWS * IN_STRIDE];  // 11.25 KB
    __shared__ __align__(16) float s_w [CI_C * 9 * CO_T];             // 18    KB

    const int tid    = threadIdx.x;
    const int b      = blockIdx.z;          // batch
    const int ty     = blockIdx.y;          // 0..7  row tile
    const int cot    = blockIdx.x >> 1;     // 0..1  co tile
    const int txt    = blockIdx.x & 1;      // 0..1  col tile
    const int y0     = ty * TH;
    const int x0     = txt * TW;
    const int co_blk = cot * CO_T;

    // Thread decomposition: warp-uniform co group, 32 spatial slots per warp.
    const int cog      = tid >> 5;          // 0..7  -> co_base = cog*8 (warp-uniform)
    const int s        = tid & 31;
    const int sr       = s >> 3;            // 0..3
    const int sc       = s & 7;             // 0..7
    const int row_base = sr * 2;            // 0,2,4,6
    const int col_base = sc * 4;            // 0,4,...,28  (16B aligned in smem)
    const int co_base  = cog * 8;

    float acc[8][2][4];
    #pragma unroll
    for (int o = 0; o < 8; ++o)
        #pragma unroll
        for (int r = 0; r < 2; ++r)
            #pragma unroll
            for (int c = 0; c < 4; ++c)
                acc[o][r][c] = 0.0f;

    const float* xb = x + (size_t)b * CI * H * W;

    #pragma unroll 1
    for (int cc = 0; cc < CI / CI_C; ++cc) {
        const int ci0 = cc * CI_C;

        // ---- Stage weights: s_w[(ci_l*9 + kk)*64 + co] = w[co_blk+co][ci0+ci_l][kk]
        #pragma unroll 1
        for (int i = tid; i < CI_C * 9 * CO_T; i += THREADS) {
            const int co  = i & 63;
            const int rem = i >> 6;         // ci_l*9 + kk, 0..71
            const int kk  = rem % 9;
            const int cil = rem / 9;
            s_w[i] = wgt[((size_t)(co_blk + co) * CI + (ci0 + cil)) * 9 + kk];
        }

        // ---- Stage input tile: 8 ch x 10 rows x 34 cols, zero-padded at edges
        #pragma unroll 1
        for (int i = tid; i < CI_C * IN_ROWS * IN_COLS; i += THREADS) {
            const int c   = i % IN_COLS;
            const int t2  = i / IN_COLS;
            const int r   = t2 % IN_ROWS;
            const int cil = t2 / IN_ROWS;
            const int gy  = y0 + r;
            const int gx  = x0 + c;
            float v = 0.0f;
            if (gy < H && gx < W)
                v = xb[((size_t)(ci0 + cil) * H + gy) * W + gx];
            s_in[(cil * IN_ROWS + r) * IN_STRIDE + c] = v;
        }
        __syncthreads();

        // ---- Compute: 8 ci x 3 ky x 3 kx, 64 FFMA per tap per thread
        #pragma unroll 1
        for (int cil = 0; cil < CI_C; ++cil) {
            #pragma unroll
            for (int ky = 0; ky < 3; ++ky) {
                const float* r0p =
                    &s_in[(cil * IN_ROWS + row_base + ky) * IN_STRIDE + col_base];
                const float* r1p = r0p + IN_STRIDE;
                // 2x6 input window covers kx=0..2 for 4 output cols
                const float4 t0 = *reinterpret_cast<const float4*>(r0p);
                const float2 u0 = *reinterpret_cast<const float2*>(r0p + 4);
                const float4 t1 = *reinterpret_cast<const float4*>(r1p);
                const float2 u1 = *reinterpret_cast<const float2*>(r1p + 4);
                const float v0[6] = {t0.x, t0.y, t0.z, t0.w, u0.x, u0.y};
                const float v1[6] = {t1.x, t1.y, t1.z, t1.w, u1.x, u1.y};

                #pragma unroll
                for (int kx = 0; kx < 3; ++kx) {
                    const int wbase = ((cil * 9 + ky * 3 + kx) << 6) + co_base;
                    const float4 wa = *reinterpret_cast<const float4*>(&s_w[wbase]);
                    const float4 wb = *reinterpret_cast<const float4*>(&s_w[wbase + 4]);
                    const float wv[8] = {wa.x, wa.y, wa.z, wa.w,
                                         wb.x, wb.y, wb.z, wb.w};
                    #pragma unroll
                    for (int o = 0; o < 8; ++o) {
                        #pragma unroll
                        for (int c = 0; c < 4; ++c) {
                            acc[o][0][c] = fmaf(wv[o], v0[kx + c], acc[o][0][c]);
                            acc[o][1][c] = fmaf(wv[o], v1[kx + c], acc[o][1][c]);
                        }
                    }
                }
            }
        }
        __syncthreads();
    }

    // ---- Epilogue: bias + bounded store
    #pragma unroll
    for (int o = 0; o < 8; ++o) {
        const int co   = co_blk + co_base + o;
        const float bv = bias[co];
        float* op = out + ((size_t)b * CO + co) * (OH * OW);
        #pragma unroll
        for (int r = 0; r < 2; ++r) {
            const int y = y0 + row_base + r;
            if (y >= OH) continue;
            #pragma unroll
            for (int c = 0; c < 4; ++c) {
                const int xq = x0 + col_base + c;
                if (xq < OW)
                    op[y * OW + xq] = acc[o][r][c] + bv;
            }
        }
    }
}

} // namespace

extern "C" void kernel_launch(void* const* d_in, const int* in_sizes, int n_in,
                              void* d_out, int out_size) {
    // Robust input identification by element count (expected order: x, weight, bias)
    const float* x    = nullptr;
    const float* wgt  = nullptr;
    const float* bias = nullptr;
    for (int i = 0; i < n_in; ++i) {
        const int sz = in_sizes[i];
        if (sz == BATCH * CI * H * W)      x    = (const float*)d_in[i];
        else if (sz == CO * CI * 9)        wgt  = (const float*)d_in[i];
        else if (sz == CO)                 bias = (const float*)d_in[i];
    }
    if (!x)    x    = (const float*)d_in[0];
    if (!wgt)  wgt  = (const float*)d_in[1];
    if (!bias) bias = (const float*)d_in[2];

    float* out = (float*)d_out;
    (void)out_size;

    // grid: x = {co_tile(2) x col_tile(2)} = 4, y = row tiles (8), z = batch (64)
    dim3 grid(4, 8, BATCH);
    dim3 block(THREADS);
    conv2d_k3_kernel<<<grid, block>>>(x, wgt, bias, out);
}

// round 5
// speedup vs baseline: 1.4004x; 1.4004x over previous
#include <cuda_runtime.h>
#include <cuda_bf16.h>
#include <cstdint>

// MyConv2D via implicit GEMM on warp-level mma.sync (bf16 hi/lo 3-pass).
// tcgen05 is rejected by this harness's ptxas target (sm_103 without 'a'),
// so we use base-arch mma.sync.m16n8k16 + ldmatrix (legacy HMMA path).
//
// x:[64,64,64,64]f32  w:[128,64,3,3]f32  bias:[128]f32 -> out:[64,128,62,62]f32
// GEMM: D[co][n] = sum_k W[co][k] * X[n][k], k=(tap,ci), n=pixel.
// CTA: M=128 co x N=128 px (2 out rows x 64 cols, cols 62/63 pad),
// K in 9 chunks of 64 (one 3x3 tap x 64 ci).
// Split v = hi + lo (bf16): D += Ah*Bh + Al*Bh + Ah*Bl  (~1e-5 rel err).

namespace {

constexpr int CIn = 64, COut = 128, H = 64, W = 64, OH = 62, OW = 62;
constexpr int BATCH = 64;
constexpr int THREADS = 256;
constexpr int TILES_PER_B = 31;            // 31 x 2 rows = 62 output rows

// smem byte offsets (dynamic smem)
constexpr int SM_A_HI = 0;                 // 128 co x 64 k bf16, SW128   (16 KB)
constexpr int SM_A_LO = 16384;
constexpr int SM_B_HI = 32768;             // 128 n  x 64 k bf16, SW128   (16 KB)
constexpr int SM_B_LO = 49152;
constexpr int SM_X    = 65536;             // 64 ci x 128 n fp32 staging  (32 KB)
constexpr int SM_TOTAL = SM_X + 64 * 128 * 4;   // 98304 B

// preconverted weights: [kk][co][ci] bf16
__device__ __align__(16) __nv_bfloat16 g_whi[9 * 128 * 64];
__device__ __align__(16) __nv_bfloat16 g_wlo[9 * 128 * 64];

__device__ __forceinline__ uint32_t smem_u32(const void* p) {
    uint32_t a;
    asm("{ .reg .u64 t; cvta.to.shared.u64 t, %1; cvt.u32.u64 %0, t; }"
        : "=r"(a) : "l"(p));
    return a;
}
__device__ __forceinline__ uint32_t sw128(uint32_t off) {
    return off ^ ((off >> 3) & 0x70);
}

#define STS128(r0, r1, r2, r3, a) \
    asm volatile("st.shared.v4.b32 [%0], {%1, %2, %3, %4};" \
                 :: "r"(a), "r"(r0), "r"(r1), "r"(r2), "r"(r3) : "memory")

__device__ __forceinline__ void ldm_x4(uint32_t& r0, uint32_t& r1,
                                       uint32_t& r2, uint32_t& r3, uint32_t a) {
    asm volatile("ldmatrix.sync.aligned.m8n8.x4.shared.b16 {%0,%1,%2,%3}, [%4];"
                 : "=r"(r0), "=r"(r1), "=r"(r2), "=r"(r3) : "r"(a));
}

__device__ __forceinline__ void mma_bf16(float* c, const uint32_t* a,
                                         const uint32_t* b) {
    asm volatile(
        "mma.sync.aligned.m16n8k16.row.col.f32.bf16.bf16.f32 "
        "{%0,%1,%2,%3}, {%4,%5,%6,%7}, {%8,%9}, {%0,%1,%2,%3};"
        : "+f"(c[0]), "+f"(c[1]), "+f"(c[2]), "+f"(c[3])
        : "r"(a[0]), "r"(a[1]), "r"(a[2]), "r"(a[3]), "r"(b[0]), "r"(b[1]));
}

// ---- weight preconvert: w[co][ci][kk] -> g_w{hi,lo}[kk][co][ci] ----
__global__ void wsplit_kernel(const float* __restrict__ w) {
    int i = blockIdx.x * blockDim.x + threadIdx.x;
    if (i >= 9 * 128 * 64) return;
    int ci = i & 63;
    int co = (i >> 6) & 127;
    int kk = i >> 13;
    float v = w[(co * CIn + ci) * 9 + kk];
    __nv_bfloat16 h = __float2bfloat16(v);
    g_whi[i] = h;
    g_wlo[i] = __float2bfloat16(v - __bfloat162float(h));
}

// ---- main kernel ----
__global__ __launch_bounds__(THREADS, 1)
void conv_mma_kernel(const float* __restrict__ x,
                     const float* __restrict__ bias,
                     float* __restrict__ out) {
    extern __shared__ __align__(1024) char smem[];
    const uint32_t sb  = smem_u32(smem);
    const int tid = threadIdx.x, wid = tid >> 5, lid = tid & 31;
    const int b   = blockIdx.x / TILES_PER_B;
    const int t   = blockIdx.x - b * TILES_PER_B;
    const int oy0 = t * 2;

    const int wm = wid & 3;        // M group: co rows [wm*32, +32)
    const int wn = wid >> 2;       // N group: px cols [wn*64, +64) (= out row wn)

    // --- precomputed ldmatrix per-lane addressing (SW128 rows of 128B) ---
    // A: row = wm*32 + mt*16 + (lid&15); koff = ks*32 + (lid>>4)*16
    const uint32_t a_xm   = (uint32_t)(lid & 7) << 4;          // row&7 -> bits 4-6
    const uint32_t a_rb0  = (uint32_t)(wm * 32 + (lid & 15)) * 128;
    const uint32_t a_kadd = (uint32_t)(lid >> 4) * 16;
    // B: row = wn*64 + i*16 + ((lid>>4)&1)*8 + (lid&7); koff = ks*32 + ((lid>>3)&1)*16
    const uint32_t b_xm   = (uint32_t)(lid & 7) << 4;
    const uint32_t b_rb0  = (uint32_t)(wn * 64 + ((lid >> 4) & 1) * 8 + (lid & 7)) * 128;
    const uint32_t b_kadd = (uint32_t)((lid >> 3) & 1) * 16;

    float acc[2][8][4];
    #pragma unroll
    for (int m = 0; m < 2; ++m)
        #pragma unroll
        for (int n = 0; n < 8; ++n)
            #pragma unroll
            for (int q = 0; q < 4; ++q)
                acc[m][n][q] = 0.0f;

    const float* xb = x + (size_t)b * CIn * H * W;
    float* s_x = reinterpret_cast<float*>(smem + SM_X);

    #pragma unroll 1
    for (int kk = 0; kk < 9; ++kk) {
        const int ky = kk / 3;
        const int kx = kk - ky * 3;

        // ---- phase 1: coalesced gather x -> s_x[ci][n]  (n = r*64 + c) ----
        #pragma unroll 8
        for (int it = 0; it < 32; ++it) {
            int i  = tid + it * THREADS;
            int c  = i & 63;
            int r  = (i >> 6) & 1;
            int ci = i >> 7;
            int gx = c + kx;
            float v = (gx < W) ? __ldg(&xb[(ci * H + (oy0 + r + ky)) * W + gx]) : 0.0f;
            s_x[(ci << 7) + (r << 6) + c] = v;
        }
        __syncthreads();   // s_x ready; also: all prior-chunk tile reads done

        // ---- phase 2: transpose + hi/lo convert -> B tiles (SW128) ----
        #pragma unroll
        for (int it = 0; it < 4; ++it) {
            int i   = tid + it * THREADS;
            int n   = i & 127;
            int grp = i >> 7;                      // 8 k-elements per group
            uint32_t hp[4], lp[4];
            #pragma unroll
            for (int j = 0; j < 4; ++j) {
                float v0 = s_x[((grp << 3) + 2 * j)     * 128 + n];
                float v1 = s_x[((grp << 3) + 2 * j + 1) * 128 + n];
                __nv_bfloat16 h0 = __float2bfloat16(v0);
                __nv_bfloat16 h1 = __float2bfloat16(v1);
                __nv_bfloat16 l0 = __float2bfloat16(v0 - __bfloat162float(h0));
                __nv_bfloat16 l1 = __float2bfloat16(v1 - __bfloat162float(h1));
                hp[j] = (uint32_t)__bfloat16_as_ushort(h0) |
                        ((uint32_t)__bfloat16_as_ushort(h1) << 16);
                lp[j] = (uint32_t)__bfloat16_as_ushort(l0) |
                        ((uint32_t)__bfloat16_as_ushort(l1) << 16);
            }
            uint32_t sw = sw128((uint32_t)(n * 128 + grp * 16));
            STS128(hp[0], hp[1], hp[2], hp[3], sb + SM_B_HI + sw);
            STS128(lp[0], lp[1], lp[2], lp[3], sb + SM_B_LO + sw);
        }

        // ---- stage A tiles: preconverted weights straight copy (SW128) ----
        {
            const __nv_bfloat16* whk = g_whi + kk * 8192;
            const __nv_bfloat16* wlk = g_wlo + kk * 8192;
            #pragma unroll
            for (int it = 0; it < 4; ++it) {
                int i   = tid + it * THREADS;
                int co  = i & 127;
                int grp = i >> 7;
                uint4 hv = *reinterpret_cast<const uint4*>(whk + co * 64 + grp * 8);
                uint4 lv = *reinterpret_cast<const uint4*>(wlk + co * 64 + grp * 8);
                uint32_t sw = sw128((uint32_t)(co * 128 + grp * 16));
                STS128(hv.x, hv.y, hv.z, hv.w, sb + SM_A_HI + sw);
                STS128(lv.x, lv.y, lv.z, lv.w, sb + SM_A_LO + sw);
            }
        }
        __syncthreads();   // tiles ready

        // ---- compute: 4 k16-steps, 3 passes each ----
        #pragma unroll
        for (int ks = 0; ks < 4; ++ks) {
            const uint32_t ka = (uint32_t)(ks * 32);
            const uint32_t aoff = (ka + a_kadd) ^ a_xm;
            const uint32_t boff = (ka + b_kadd) ^ b_xm;

            uint32_t bh[16], ah[8], al[8];
            // B-hi: 4 x4-loads, each covering 2 n8-tiles
            #pragma unroll
            for (int i2 = 0; i2 < 4; ++i2)
                ldm_x4(bh[i2 * 4 + 0], bh[i2 * 4 + 1], bh[i2 * 4 + 2], bh[i2 * 4 + 3],
                       sb + SM_B_HI + b_rb0 + (uint32_t)(i2 * 16 * 128) + boff);
            // A-hi: 2 x4-loads (mt = 0,1)
            #pragma unroll
            for (int m = 0; m < 2; ++m)
                ldm_x4(ah[m * 4 + 0], ah[m * 4 + 1], ah[m * 4 + 2], ah[m * 4 + 3],
                       sb + SM_A_HI + a_rb0 + (uint32_t)(m * 16 * 128) + aoff);
            // pass HH
            #pragma unroll
            for (int m = 0; m < 2; ++m)
                #pragma unroll
                for (int n = 0; n < 8; ++n)
                    mma_bf16(acc[m][n], ah + m * 4, bh + (n >> 1) * 4 + (n & 1) * 2);
            // A-lo
            #pragma unroll
            for (int m = 0; m < 2; ++m)
                ldm_x4(al[m * 4 + 0], al[m * 4 + 1], al[m * 4 + 2], al[m * 4 + 3],
                       sb + SM_A_LO + a_rb0 + (uint32_t)(m * 16 * 128) + aoff);
            // pass LH
            #pragma unroll
            for (int m = 0; m < 2; ++m)
                #pragma unroll
                for (int n = 0; n < 8; ++n)
                    mma_bf16(acc[m][n], al + m * 4, bh + (n >> 1) * 4 + (n & 1) * 2);
            // B-lo (reuse bh regs)
            #pragma unroll
            for (int i2 = 0; i2 < 4; ++i2)
                ldm_x4(bh[i2 * 4 + 0], bh[i2 * 4 + 1], bh[i2 * 4 + 2], bh[i2 * 4 + 3],
                       sb + SM_B_LO + b_rb0 + (uint32_t)(i2 * 16 * 128) + boff);
            // pass HL
            #pragma unroll
            for (int m = 0; m < 2; ++m)
                #pragma unroll
                for (int n = 0; n < 8; ++n)
                    mma_bf16(acc[m][n], ah + m * 4, bh + (n >> 1) * 4 + (n & 1) * 2);
        }
    }

    // ---- epilogue: bias + store (register accums -> gmem) ----
    // thread holds: rows co = wm*32 + mt*16 + (lid>>2) and +8;
    //               cols n  = nt*8 + (lid&3)*2 + {0,1}  (within this warp's 64)
    const int oy = oy0 + wn;
    #pragma unroll
    for (int m = 0; m < 2; ++m) {
        const int co0 = wm * 32 + m * 16 + (lid >> 2);
        const float bv0 = __ldg(&bias[co0]);
        const float bv1 = __ldg(&bias[co0 + 8]);
        float* op0 = out + ((size_t)(b * COut + co0)     * OH + oy) * OW;
        float* op1 = out + ((size_t)(b * COut + co0 + 8) * OH + oy) * OW;
        #pragma unroll
        for (int n = 0; n < 8; ++n) {
            const int col = n * 8 + (lid & 3) * 2;
            if (col < OW) {   // col is even; col==62 -> pair (62,63) both pad
                float2 v0 = make_float2(acc[m][n][0] + bv0, acc[m][n][1] + bv0);
                float2 v1 = make_float2(acc[m][n][2] + bv1, acc[m][n][3] + bv1);
                *reinterpret_cast<float2*>(op0 + col) = v0;
                *reinterpret_cast<float2*>(op1 + col) = v1;
            }
        }
    }
}

} // namespace

extern "C" void kernel_launch(void* const* d_in, const int* in_sizes, int n_in,
                              void* d_out, int out_size) {
    const float* x    = nullptr;
    const float* wgt  = nullptr;
    const float* bias = nullptr;
    for (int i = 0; i < n_in; ++i) {
        const int sz = in_sizes[i];
        if (sz == BATCH * CIn * H * W) x    = (const float*)d_in[i];
        else if (sz == COut * CIn * 9) wgt  = (const float*)d_in[i];
        else if (sz == COut)           bias = (const float*)d_in[i];
    }
    if (!x)    x    = (const float*)d_in[0];
    if (!wgt)  wgt  = (const float*)d_in[1];
    if (!bias) bias = (const float*)d_in[2];
    float* out = (float*)d_out;
    (void)out_size;

    cudaFuncSetAttribute(conv_mma_kernel,
                         cudaFuncAttributeMaxDynamicSharedMemorySize, SM_TOTAL);

    wsplit_kernel<<<(9 * 128 * 64 + 255) / 256, 256>>>(wgt);
    conv_mma_kernel<<<BATCH * TILES_PER_B, THREADS, SM_TOTAL>>>(x, bias, out);
}

// round 6
// speedup vs baseline: 3.0190x; 2.1558x over previous
#include <cuda_runtime.h>
#include <cuda_bf16.h>
#include <cstdint>

// MyConv2D via implicit GEMM on warp-level mma.sync (bf16 hi/lo 3-pass).
// R6: input halo staged ONCE per CTA (all 9 taps read shifted views);
//     weight tiles double-buffered via cp.async, overlapped with MMA.
//
// x:[64,64,64,64]f32  w:[128,64,3,3]f32  bias:[128]f32 -> out:[64,128,62,62]f32
// GEMM: D[co][n] = sum_k W[co][k] * X[n][k], k=(tap,ci), n=pixel.
// CTA: M=128 co x N=128 px (2 out rows x 64 cols), K = 9 taps x 64 ci.
// Split v = hi + lo (bf16): D += Ah*Bh + Al*Bh + Ah*Bl  (~5e-6 rel err).

namespace {

constexpr int CIn = 64, COut = 128, H = 64, W = 64, OH = 62, OW = 62;
constexpr int BATCH = 64;
constexpr int THREADS = 256;
constexpr int TILES_PER_B = 31;            // 31 x 2 out rows = 62

// ---- smem byte offsets (dynamic) ----
// A double buffer: buf k -> hi at +0, lo at +16384 (each 128co x 64k bf16 SW128)
constexpr int SM_A0    = 0;                // 32 KB
constexpr int SM_A1    = 32768;            // 32 KB
constexpr int SM_B_HI  = 65536;            // 264 px x 64 ci bf16 SW128 = 33792 B
constexpr int SM_B_LO  = 99328;            // 33792 B
constexpr int SM_X     = 133120;           // 64 ci x 136 fp32 staging = 34816 B
constexpr int SM_TOTAL = 167936;
constexpr int B_LO_DELTA = SM_B_LO - SM_B_HI;   // 33792

// preconverted weights: [kk][co][ci] bf16
__device__ __align__(16) __nv_bfloat16 g_whi[9 * 128 * 64];
__device__ __align__(16) __nv_bfloat16 g_wlo[9 * 128 * 64];

__device__ __forceinline__ uint32_t smem_u32(const void* p) {
    uint32_t a;
    asm("{ .reg .u64 t; cvta.to.shared.u64 t, %1; cvt.u32.u64 %0, t; }"
        : "=r"(a) : "l"(p));
    return a;
}
__device__ __forceinline__ uint32_t sw128(uint32_t off) {
    return off ^ ((off >> 3) & 0x70);
}
__device__ __forceinline__ uint64_t to_global(const void* p) {
    uint64_t g;
    asm("cvta.to.global.u64 %0, %1;" : "=l"(g) : "l"(p));
    return g;
}

#define STS128(r0, r1, r2, r3, a) \
    asm volatile("st.shared.v4.b32 [%0], {%1, %2, %3, %4};" \
                 :: "r"(a), "r"(r0), "r"(r1), "r"(r2), "r"(r3) : "memory")
#define STS128F(f0, f1, f2, f3, a) \
    asm volatile("st.shared.v4.f32 [%0], {%1, %2, %3, %4};" \
                 :: "r"(a), "f"(f0), "f"(f1), "f"(f2), "f"(f3) : "memory")
#define CP_ASYNC16(dst, src) \
    asm volatile("cp.async.cg.shared.global [%0], [%1], 16;" \
                 :: "r"(dst), "l"(src) : "memory")
#define CP_COMMIT() asm volatile("cp.async.commit_group;" ::: "memory")
#define CP_WAIT0()  asm volatile("cp.async.wait_group 0;" ::: "memory")

__device__ __forceinline__ void ldm_x4(uint32_t& r0, uint32_t& r1,
                                       uint32_t& r2, uint32_t& r3, uint32_t a) {
    asm volatile("ldmatrix.sync.aligned.m8n8.x4.shared.b16 {%0,%1,%2,%3}, [%4];"
                 : "=r"(r0), "=r"(r1), "=r"(r2), "=r"(r3) : "r"(a));
}
__device__ __forceinline__ void mma_bf16(float* c, const uint32_t* a,
                                         const uint32_t* b) {
    asm volatile(
        "mma.sync.aligned.m16n8k16.row.col.f32.bf16.bf16.f32 "
        "{%0,%1,%2,%3}, {%4,%5,%6,%7}, {%8,%9}, {%0,%1,%2,%3};"
        : "+f"(c[0]), "+f"(c[1]), "+f"(c[2]), "+f"(c[3])
        : "r"(a[0]), "r"(a[1]), "r"(a[2]), "r"(a[3]), "r"(b[0]), "r"(b[1]));
}

// ---- weight preconvert: w[co][ci][kk] -> g_w{hi,lo}[kk][co][ci] ----
__global__ void wsplit_kernel(const float* __restrict__ w) {
    int i = blockIdx.x * blockDim.x + threadIdx.x;
    if (i >= 9 * 128 * 64) return;
    int ci = i & 63;
    int co = (i >> 6) & 127;
    int kk = i >> 13;
    float v = w[(co * CIn + ci) * 9 + kk];
    __nv_bfloat16 h = __float2bfloat16(v);
    g_whi[i] = h;
    g_wlo[i] = __float2bfloat16(v - __bfloat162float(h));
}

// prefetch one tap's A tiles (hi+lo) into smem buffer via cp.async
__device__ __forceinline__ void prefetch_A(int kk, uint32_t dst, int tid) {
    const uint64_t whk = to_global(g_whi) + (uint64_t)kk * 8192 * 2;
    const uint64_t wlk = to_global(g_wlo) + (uint64_t)kk * 8192 * 2;
    #pragma unroll
    for (int it = 0; it < 4; ++it) {
        int i   = tid + it * THREADS;        // 0..1023
        int co  = i & 127;
        int grp = i >> 7;
        uint32_t sw   = sw128((uint32_t)(co * 128 + grp * 16));
        uint64_t soff = (uint64_t)(co * 64 + grp * 8) * 2;
        CP_ASYNC16(dst + sw,         whk + soff);
        CP_ASYNC16(dst + 16384 + sw, wlk + soff);
    }
}

// ---- main kernel ----
__global__ __launch_bounds__(THREADS, 1)
void conv_mma_kernel(const float* __restrict__ x,
                     const float* __restrict__ bias,
                     float* __restrict__ out) {
    extern __shared__ __align__(1024) char smem[];
    const uint32_t sb  = smem_u32(smem);
    const int tid = threadIdx.x, wid = tid >> 5, lid = tid & 31;
    const int b   = blockIdx.x / TILES_PER_B;
    const int t   = blockIdx.x - b * TILES_PER_B;
    const int oy0 = t * 2;

    const int wm = wid & 3;        // M group: co rows [wm*32, +32)
    const int wn = wid >> 2;       // N group: output row wn (0/1), cols 0..63

    // A ldmatrix lane addressing (within a 128x64 SW128 tile)
    const uint32_t a_xm   = (uint32_t)(lid & 7) << 4;
    const uint32_t a_rb0  = (uint32_t)(wm * 32 + (lid & 15)) * 128;
    const uint32_t a_kadd = (uint32_t)(lid >> 4) * 16;
    // B k-half select
    const uint32_t b_kadd = (uint32_t)((lid >> 3) & 1) * 16;

    float acc[2][8][4];
    #pragma unroll
    for (int m = 0; m < 2; ++m)
        #pragma unroll
        for (int n = 0; n < 8; ++n)
            #pragma unroll
            for (int q = 0; q < 4; ++q)
                acc[m][n][q] = 0.0f;

    const float* xb = x + (size_t)b * CIn * H * W;
    float* s_x = reinterpret_cast<float*>(smem + SM_X);   // [ci][136] fp32

    // kick off A(tap0) prefetch; it overlaps the whole B staging below
    prefetch_A(0, sb + SM_A0, tid);
    CP_COMMIT();

    // ============ one-time B staging: 4 halo rows x 66 cols x 64 ci ============
    // chunk c2 stages input rows {oy0+2*c2, +1} -> pixels fpix = irow*66+icol
    #pragma unroll 1
    for (int c2 = 0; c2 < 2; ++c2) {
        // gather fp32, coalesced float4: s_x[ci][lr*68 + col]
        #pragma unroll
        for (int it = 0; it < 8; ++it) {
            int i    = tid + it * THREADS;       // 0..2047
            int qcol = i & 15;
            int lr   = (i >> 4) & 1;
            int ci   = i >> 5;
            int gy   = oy0 + c2 * 2 + lr;
            const float4 v = *reinterpret_cast<const float4*>(
                xb + ((size_t)ci * H + gy) * W + qcol * 4);
            STS128F(v.x, v.y, v.z, v.w,
                    sb + SM_X + (uint32_t)(ci * 136 + lr * 68 + qcol * 4) * 4);
        }
        {   // zero halo cols 64,65
            int ci = tid & 63, lr = (tid >> 6) & 1, cz = 64 + (tid >> 7);
            s_x[ci * 136 + lr * 68 + cz] = 0.0f;
        }
        __syncthreads();

        // convert + transpose -> B hi/lo tiles [fpix][ci] SW128
        #pragma unroll
        for (int it = 0; it < 5; ++it) {
            int i = tid + it * THREADS;          // 0..1055
            if (i < 1056) {
                int pix = i % 132;               // local pixel in this chunk
                int grp = i / 132;               // 8 ci per group
                int lr  = (pix >= 66);
                int lc  = pix + 2 * lr;          // index into padded s_x row
                uint32_t hp[4], lp[4];
                #pragma unroll
                for (int j = 0; j < 4; ++j) {
                    float v0 = s_x[((grp << 3) + 2 * j)     * 136 + lc];
                    float v1 = s_x[((grp << 3) + 2 * j + 1) * 136 + lc];
                    __nv_bfloat16 h0 = __float2bfloat16(v0);
                    __nv_bfloat16 h1 = __float2bfloat16(v1);
                    __nv_bfloat16 l0 = __float2bfloat16(v0 - __bfloat162float(h0));
                    __nv_bfloat16 l1 = __float2bfloat16(v1 - __bfloat162float(h1));
                    hp[j] = (uint32_t)__bfloat16_as_ushort(h0) |
                            ((uint32_t)__bfloat16_as_ushort(h1) << 16);
                    lp[j] = (uint32_t)__bfloat16_as_ushort(l0) |
                            ((uint32_t)__bfloat16_as_ushort(l1) << 16);
                }
                uint32_t fpix = (uint32_t)(c2 * 132 + pix);
                uint32_t adr  = fpix * 128 +
                                (((uint32_t)grp * 16) ^ ((fpix & 7) << 4));
                STS128(hp[0], hp[1], hp[2], hp[3], sb + SM_B_HI + adr);
                STS128(lp[0], lp[1], lp[2], lp[3], sb + SM_B_LO + adr);
            }
        }
        __syncthreads();
    }

    // ============ main loop: 9 taps, A double-buffered via cp.async ============
    #pragma unroll 1
    for (int kk = 0; kk < 9; ++kk) {
        CP_WAIT0();          // A(kk) resident
        __syncthreads();     // all warps done with tap kk-1; A visible CTA-wide
        if (kk < 8) {
            prefetch_A(kk + 1, sb + ((kk + 1) & 1 ? SM_A1 : SM_A0), tid);
            CP_COMMIT();
        }

        const uint32_t ab = sb + ((kk & 1) ? SM_A1 : SM_A0);
        const int ky = kk / 3, kx = kk - 3 * ky;
        // this warp's B lane pixel for tap (ky,kx)
        const uint32_t lanepix =
            (uint32_t)((wn + ky) * 66 + kx + ((lid >> 4) & 1) * 8 + (lid & 7));
        const uint32_t b_base = sb + SM_B_HI + lanepix * 128;
        const uint32_t b_xm2  = (lanepix & 7) << 4;

        #pragma unroll
        for (int ks = 0; ks < 4; ++ks) {
            const uint32_t aoff = ((uint32_t)(ks * 32) + a_kadd) ^ a_xm;
            const uint32_t boff = ((uint32_t)(ks * 32) + b_kadd) ^ b_xm2;

            uint32_t bh[16], ah[8], al[8];
            #pragma unroll
            for (int i2 = 0; i2 < 4; ++i2)
                ldm_x4(bh[i2 * 4 + 0], bh[i2 * 4 + 1], bh[i2 * 4 + 2], bh[i2 * 4 + 3],
                       b_base + (uint32_t)(i2 * 2048) + boff);
            #pragma unroll
            for (int m = 0; m < 2; ++m)
                ldm_x4(ah[m * 4 + 0], ah[m * 4 + 1], ah[m * 4 + 2], ah[m * 4 + 3],
                       ab + a_rb0 + (uint32_t)(m * 16 * 128) + aoff);
            #pragma unroll
            for (int m = 0; m < 2; ++m)         // HH
                #pragma unroll
                for (int n = 0; n < 8; ++n)
                    mma_bf16(acc[m][n], ah + m * 4, bh + (n >> 1) * 4 + (n & 1) * 2);
            #pragma unroll
            for (int m = 0; m < 2; ++m)
                ldm_x4(al[m * 4 + 0], al[m * 4 + 1], al[m * 4 + 2], al[m * 4 + 3],
                       ab + 16384 + a_rb0 + (uint32_t)(m * 16 * 128) + aoff);
            #pragma unroll
            for (int m = 0; m < 2; ++m)         // LH
                #pragma unroll
                for (int n = 0; n < 8; ++n)
                    mma_bf16(acc[m][n], al + m * 4, bh + (n >> 1) * 4 + (n & 1) * 2);
            #pragma unroll
            for (int i2 = 0; i2 < 4; ++i2)      // B-lo reuses bh regs
                ldm_x4(bh[i2 * 4 + 0], bh[i2 * 4 + 1], bh[i2 * 4 + 2], bh[i2 * 4 + 3],
                       b_base + B_LO_DELTA + (uint32_t)(i2 * 2048) + boff);
            #pragma unroll
            for (int m = 0; m < 2; ++m)         // HL
                #pragma unroll
                for (int n = 0; n < 8; ++n)
                    mma_bf16(acc[m][n], ah + m * 4, bh + (n >> 1) * 4 + (n & 1) * 2);
        }
    }

    // ============ epilogue: bias + store ============
    const int oy = oy0 + wn;
    #pragma unroll
    for (int m = 0; m < 2; ++m) {
        const int co0 = wm * 32 + m * 16 + (lid >> 2);
        const float bv0 = __ldg(&bias[co0]);
        const float bv1 = __ldg(&bias[co0 + 8]);
        float* op0 = out + ((size_t)(b * COut + co0)     * OH + oy) * OW;
        float* op1 = out + ((size_t)(b * COut + co0 + 8) * OH + oy) * OW;
        #pragma unroll
        for (int n = 0; n < 8; ++n) {
            const int col = n * 8 + (lid & 3) * 2;
            if (col < OW) {
                float2 v0 = make_float2(acc[m][n][0] + bv0, acc[m][n][1] + bv0);
                float2 v1 = make_float2(acc[m][n][2] + bv1, acc[m][n][3] + bv1);
                *reinterpret_cast<float2*>(op0 + col) = v0;
                *reinterpret_cast<float2*>(op1 + col) = v1;
            }
        }
    }
}

} // namespace

extern "C" void kernel_launch(void* const* d_in, const int* in_sizes, int n_in,
                              void* d_out, int out_size) {
    const float* x    = nullptr;
    const float* wgt  = nullptr;
    const float* bias = nullptr;
    for (int i = 0; i < n_in; ++i) {
        const int sz = in_sizes[i];
        if (sz == BATCH * CIn * H * W) x    = (const float*)d_in[i];
        else if (sz == COut * CIn * 9) wgt  = (const float*)d_in[i];
        else if (sz == COut)           bias = (const float*)d_in[i];
    }
    if (!x)    x    = (const float*)d_in[0];
    if (!wgt)  wgt  = (const float*)d_in[1];
    if (!bias) bias = (const float*)d_in[2];
    float* out = (float*)d_out;
    (void)out_size;

    cudaFuncSetAttribute(conv_mma_kernel,
                         cudaFuncAttributeMaxDynamicSharedMemorySize, SM_TOTAL);

    wsplit_kernel<<<(9 * 128 * 64 + 255) / 256, 256>>>(wgt);
    conv_mma_kernel<<<BATCH * TILES_PER_B, THREADS, SM_TOTAL>>>(x, bias, out);
}